// round 13
// baseline (speedup 1.0000x reference)
#include <cuda_runtime.h>

#define C_CH   128
#define NGROUP 32
#define CPG    4
#define BMAX   64
#define EPSF   1e-5f

// Scratch (no allocations allowed)
__device__ double g_sum[BMAX * C_CH];
__device__ double g_sqs[BMAX * C_CH];
__device__ int    g_bounds[BMAX + 1];
__device__ int    g_nseg;
__device__ float4 g_scale[BMAX * NGROUP];
__device__ float4 g_shift[BMAX * NGROUP];

// ---------------------------------------------------------------------------
// 0) setup: zero accumulators + segment bounds by binary search.
// ---------------------------------------------------------------------------
__global__ void dogn_setup(const int* __restrict__ bid, int n,
                           const int* __restrict__ bsz_ptr) {
    if (blockIdx.x < 16) {
        int i = blockIdx.x * 512 + threadIdx.x;
        if (i < BMAX * C_CH) {
            g_sum[i] = 0.0;
            g_sqs[i] = 0.0;
        }
    } else {
        int B = __ldg(bsz_ptr);
        if (B > BMAX) B = BMAX;
        int t = threadIdx.x;
        if (t == 0) g_nseg = B;
        if (t <= B) {
            int lo = 0, hi = n;
            while (lo < hi) {
                int mid = (lo + hi) >> 1;
                if (__ldg(&bid[mid]) < t) lo = mid + 1;
                else hi = mid;
            }
            g_bounds[t] = lo;
        }
    }
}

// ---------------------------------------------------------------------------
// 1) stats: block owns contiguous row chunk; per overlapping segment a pure
//    ldcs->FMA stream (4-row unroll); flush via cross-warp smem reduction,
//    warp 0 issues the atomics.
// ---------------------------------------------------------------------------
#define ACC4(v)                                   \
    s0 += (v).x; q0 = fmaf((v).x, (v).x, q0);     \
    s1 += (v).y; q1 = fmaf((v).y, (v).y, q1);     \
    s2 += (v).z; q2 = fmaf((v).z, (v).z, q2);     \
    s3 += (v).w; q3 = fmaf((v).w, (v).w, q3);

__global__ void dogn_stats(const float4* __restrict__ data,
                           int n, int rows_per_block) {
    __shared__ int   sb[BMAX + 1];
    __shared__ int   sB;
    __shared__ float red[8 * 256];   // [k][warp*32 + lane]

    if (threadIdx.x == 0) sB = g_nseg;
    __syncthreads();
    int B = sB;
    for (int j = threadIdx.x; j <= B; j += blockDim.x) sb[j] = g_bounds[j];
    __syncthreads();

    const int tid  = threadIdx.x;
    const int lane = tid & 31;
    const int rsub = tid >> 5;
    int r0 = blockIdx.x * rows_per_block;
    int r1 = r0 + rows_per_block;
    if (r1 > n) r1 = n;
    // No early-return: segment loop stays block-uniform for __syncthreads.

    for (int seg = 0; seg < B; seg++) {
        int a = sb[seg], e = sb[seg + 1];
        if (a < r0) a = r0;
        if (e > r1) e = r1;
        if (a >= e) continue;   // block-uniform

        float s0 = 0.f, s1 = 0.f, s2 = 0.f, s3 = 0.f;
        float q0 = 0.f, q1 = 0.f, q2 = 0.f, q3 = 0.f;

        int r = a + rsub;
        for (; r + 24 < e; r += 32) {
            const float4* p = &data[(size_t)r * 32 + lane];
            float4 v0 = __ldcs(p);
            float4 v1 = __ldcs(p + 8 * 32);
            float4 v2 = __ldcs(p + 16 * 32);
            float4 v3 = __ldcs(p + 24 * 32);
            ACC4(v0) ACC4(v1) ACC4(v2) ACC4(v3)
        }
        for (; r < e; r += 8) {
            float4 v = __ldcs(&data[(size_t)r * 32 + lane]);
            ACC4(v)
        }

        red[0 * 256 + tid] = s0;
        red[1 * 256 + tid] = s1;
        red[2 * 256 + tid] = s2;
        red[3 * 256 + tid] = s3;
        red[4 * 256 + tid] = q0;
        red[5 * 256 + tid] = q1;
        red[6 * 256 + tid] = q2;
        red[7 * 256 + tid] = q3;
        __syncthreads();

        if (tid < 32) {
            double* ps = &g_sum[seg * C_CH + tid * 4];
            double* pq = &g_sqs[seg * C_CH + tid * 4];
#pragma unroll
            for (int k = 0; k < 4; k++) {
                float vs = 0.f, vq = 0.f;
#pragma unroll
                for (int w = 0; w < 8; w++) {
                    vs += red[k * 256 + w * 32 + tid];
                    vq += red[(k + 4) * 256 + w * 32 + tid];
                }
                atomicAdd(ps + k, (double)vs);
                atomicAdd(pq + k, (double)vq);
            }
        }
        __syncthreads();
    }
}

// ---------------------------------------------------------------------------
// 2) finalize: one block per batch, 32 threads = 32 groups.
// ---------------------------------------------------------------------------
__global__ void dogn_finalize(const float* __restrict__ w,
                              const float* __restrict__ bias) {
    int b = blockIdx.x;
    if (b >= g_nseg) return;
    int g = threadIdx.x;

    int nb = g_bounds[b + 1] - g_bounds[b];
    double ic = 1.0 / (4.0 * (double)nb + (double)EPSF);

    double T1 = 0.0, T2 = 0.0;
#pragma unroll
    for (int k = 0; k < 4; k++) {
        T1 += g_sum[b * C_CH + g * 4 + k];
        T2 += g_sqs[b * C_CH + g * 4 + k];
    }
    double m   = T1 * ic;
    double var = (T2 - 2.0 * m * T1 + 4.0 * (double)nb * m * m) * ic;
    double is  = 1.0 / sqrt(var + (double)EPSF);

    float4 sc, sh;
    float wv, bv;
    wv = __ldg(&w[g * 4 + 0]); bv = __ldg(&bias[g * 4 + 0]);
    sc.x = (float)(is * wv);   sh.x = (float)(bv - m * is * wv);
    wv = __ldg(&w[g * 4 + 1]); bv = __ldg(&bias[g * 4 + 1]);
    sc.y = (float)(is * wv);   sh.y = (float)(bv - m * is * wv);
    wv = __ldg(&w[g * 4 + 2]); bv = __ldg(&bias[g * 4 + 2]);
    sc.z = (float)(is * wv);   sh.z = (float)(bv - m * is * wv);
    wv = __ldg(&w[g * 4 + 3]); bv = __ldg(&bias[g * 4 + 3]);
    sc.w = (float)(is * wv);   sh.w = (float)(bv - m * is * wv);

    g_scale[b * NGROUP + g] = sc;
    g_shift[b * NGROUP + g] = sh;
}

// ---------------------------------------------------------------------------
// 3) normalize: inline index arithmetic, no launch bounds (measured-best
//    allocation: 48 regs / 5 CTAs/SM); pure ldcs -> FFMA -> stcs stream.
// ---------------------------------------------------------------------------
__global__ void dogn_norm(const float4* __restrict__ data,
                          float4* __restrict__ out,
                          int n, int rows_per_block) {
    __shared__ int sb[BMAX + 1];
    __shared__ int sB;
    if (threadIdx.x == 0) sB = g_nseg;
    __syncthreads();
    int B = sB;
    for (int j = threadIdx.x; j <= B; j += blockDim.x) sb[j] = g_bounds[j];
    __syncthreads();

    const int lane = threadIdx.x & 31;
    const int rsub = threadIdx.x >> 5;
    int r0 = blockIdx.x * rows_per_block;
    int r1 = r0 + rows_per_block;
    if (r1 > n) r1 = n;
    if (r0 >= r1) return;

    for (int seg = 0; seg < B; seg++) {
        int a = sb[seg], e = sb[seg + 1];
        if (a < r0) a = r0;
        if (e > r1) e = r1;
        if (a >= e) continue;

        float4 sc = g_scale[seg * NGROUP + lane];
        float4 sh = g_shift[seg * NGROUP + lane];

        int r = a + rsub;
        for (; r + 24 < e; r += 32) {
            float4 v0 = __ldcs(&data[(size_t)r * 32 + lane]);
            float4 v1 = __ldcs(&data[(size_t)(r + 8) * 32 + lane]);
            float4 v2 = __ldcs(&data[(size_t)(r + 16) * 32 + lane]);
            float4 v3 = __ldcs(&data[(size_t)(r + 24) * 32 + lane]);
            v0.x = fmaf(v0.x, sc.x, sh.x);
            v0.y = fmaf(v0.y, sc.y, sh.y);
            v0.z = fmaf(v0.z, sc.z, sh.z);
            v0.w = fmaf(v0.w, sc.w, sh.w);
            v1.x = fmaf(v1.x, sc.x, sh.x);
            v1.y = fmaf(v1.y, sc.y, sh.y);
            v1.z = fmaf(v1.z, sc.z, sh.z);
            v1.w = fmaf(v1.w, sc.w, sh.w);
            v2.x = fmaf(v2.x, sc.x, sh.x);
            v2.y = fmaf(v2.y, sc.y, sh.y);
            v2.z = fmaf(v2.z, sc.z, sh.z);
            v2.w = fmaf(v2.w, sc.w, sh.w);
            v3.x = fmaf(v3.x, sc.x, sh.x);
            v3.y = fmaf(v3.y, sc.y, sh.y);
            v3.z = fmaf(v3.z, sc.z, sh.z);
            v3.w = fmaf(v3.w, sc.w, sh.w);
            __stcs(&out[(size_t)r * 32 + lane], v0);
            __stcs(&out[(size_t)(r + 8) * 32 + lane], v1);
            __stcs(&out[(size_t)(r + 16) * 32 + lane], v2);
            __stcs(&out[(size_t)(r + 24) * 32 + lane], v3);
        }
        for (; r < e; r += 8) {
            float4 v = __ldcs(&data[(size_t)r * 32 + lane]);
            v.x = fmaf(v.x, sc.x, sh.x);
            v.y = fmaf(v.y, sc.y, sh.y);
            v.z = fmaf(v.z, sc.z, sh.z);
            v.w = fmaf(v.w, sc.w, sh.w);
            __stcs(&out[(size_t)r * 32 + lane], v);
        }
    }
}

// ---------------------------------------------------------------------------
extern "C" void kernel_launch(void* const* d_in, const int* in_sizes, int n_in,
                              void* d_out, int out_size) {
    const float* data = (const float*)d_in[0];
    const float* w    = (const float*)d_in[1];
    const float* bias = (const float*)d_in[2];
    const int*   bid  = (const int*)d_in[3];
    const int*   bsz  = (const int*)d_in[4];

    int n = in_sizes[0] / C_CH;   // rows

    dogn_setup<<<17, 512>>>(bid, n, bsz);

    // stats: fine chunks (best measured)
    const int SGRID = 3552;
    int srpb = (n + SGRID - 1) / SGRID;
    dogn_stats<<<SGRID, 256>>>((const float4*)data, n, srpb);

    dogn_finalize<<<BMAX, 32>>>(w, bias);

    // norm: fine chunks (R11 best-total configuration)
    const int NGRID = 2368;
    int nrpb = (n + NGRID - 1) / NGRID;
    dogn_norm<<<NGRID, 256>>>((const float4*)data, (float4*)d_out, n, nrpb);
}

// round 14
// speedup vs baseline: 1.0054x; 1.0054x over previous
#include <cuda_runtime.h>

#define C_CH   128
#define NGROUP 32
#define CPG    4
#define BMAX   64
#define EPSF   1e-5f

// Scratch (no allocations allowed). Zero-initialized at module load; the
// g_sum/g_sqs "zero at stats entry" invariant is restored by dogn_finalize
// re-zeroing its slice after consumption (replay-safe, deterministic).
__device__ double g_sum[BMAX * C_CH];
__device__ double g_sqs[BMAX * C_CH];
__device__ int    g_bounds[BMAX + 1];
__device__ int    g_nseg;
__device__ float4 g_scale[BMAX * NGROUP];
__device__ float4 g_shift[BMAX * NGROUP];

// ---------------------------------------------------------------------------
// 0) setup: segment bounds by binary search only (single block).
// ---------------------------------------------------------------------------
__global__ void dogn_setup(const int* __restrict__ bid, int n,
                           const int* __restrict__ bsz_ptr) {
    int B = __ldg(bsz_ptr);
    if (B > BMAX) B = BMAX;
    int t = threadIdx.x;
    if (t == 0) g_nseg = B;
    if (t <= B) {
        int lo = 0, hi = n;
        while (lo < hi) {
            int mid = (lo + hi) >> 1;
            if (__ldg(&bid[mid]) < t) lo = mid + 1;
            else hi = mid;
        }
        g_bounds[t] = lo;
    }
}

// ---------------------------------------------------------------------------
// 1) stats: block owns contiguous row chunk; per overlapping segment a pure
//    ldcs->FMA stream (4-row unroll); flush via cross-warp smem reduction,
//    warp 0 issues the atomics. (SGRID=3552, best measured)
// ---------------------------------------------------------------------------
#define ACC4(v)                                   \
    s0 += (v).x; q0 = fmaf((v).x, (v).x, q0);     \
    s1 += (v).y; q1 = fmaf((v).y, (v).y, q1);     \
    s2 += (v).z; q2 = fmaf((v).z, (v).z, q2);     \
    s3 += (v).w; q3 = fmaf((v).w, (v).w, q3);

__global__ void dogn_stats(const float4* __restrict__ data,
                           int n, int rows_per_block) {
    __shared__ int   sb[BMAX + 1];
    __shared__ int   sB;
    __shared__ float red[8 * 256];   // [k][warp*32 + lane]

    if (threadIdx.x == 0) sB = g_nseg;
    __syncthreads();
    int B = sB;
    for (int j = threadIdx.x; j <= B; j += blockDim.x) sb[j] = g_bounds[j];
    __syncthreads();

    const int tid  = threadIdx.x;
    const int lane = tid & 31;
    const int rsub = tid >> 5;
    int r0 = blockIdx.x * rows_per_block;
    int r1 = r0 + rows_per_block;
    if (r1 > n) r1 = n;
    // No early-return: segment loop stays block-uniform for __syncthreads.

    for (int seg = 0; seg < B; seg++) {
        int a = sb[seg], e = sb[seg + 1];
        if (a < r0) a = r0;
        if (e > r1) e = r1;
        if (a >= e) continue;   // block-uniform

        float s0 = 0.f, s1 = 0.f, s2 = 0.f, s3 = 0.f;
        float q0 = 0.f, q1 = 0.f, q2 = 0.f, q3 = 0.f;

        int r = a + rsub;
        for (; r + 24 < e; r += 32) {
            const float4* p = &data[(size_t)r * 32 + lane];
            float4 v0 = __ldcs(p);
            float4 v1 = __ldcs(p + 8 * 32);
            float4 v2 = __ldcs(p + 16 * 32);
            float4 v3 = __ldcs(p + 24 * 32);
            ACC4(v0) ACC4(v1) ACC4(v2) ACC4(v3)
        }
        for (; r < e; r += 8) {
            float4 v = __ldcs(&data[(size_t)r * 32 + lane]);
            ACC4(v)
        }

        red[0 * 256 + tid] = s0;
        red[1 * 256 + tid] = s1;
        red[2 * 256 + tid] = s2;
        red[3 * 256 + tid] = s3;
        red[4 * 256 + tid] = q0;
        red[5 * 256 + tid] = q1;
        red[6 * 256 + tid] = q2;
        red[7 * 256 + tid] = q3;
        __syncthreads();

        if (tid < 32) {
            double* ps = &g_sum[seg * C_CH + tid * 4];
            double* pq = &g_sqs[seg * C_CH + tid * 4];
#pragma unroll
            for (int k = 0; k < 4; k++) {
                float vs = 0.f, vq = 0.f;
#pragma unroll
                for (int w = 0; w < 8; w++) {
                    vs += red[k * 256 + w * 32 + tid];
                    vq += red[(k + 4) * 256 + w * 32 + tid];
                }
                atomicAdd(ps + k, (double)vs);
                atomicAdd(pq + k, (double)vq);
            }
        }
        __syncthreads();
    }
}

// ---------------------------------------------------------------------------
// 2) finalize: one block per batch, 32 threads = 32 groups. After consuming
//    its sums, each block RE-ZEROES its g_sum/g_sqs slice so the next graph
//    replay's stats kernel starts from zeros (replaces the setup zero pass).
// ---------------------------------------------------------------------------
__global__ void dogn_finalize(const float* __restrict__ w,
                              const float* __restrict__ bias) {
    int b = blockIdx.x;
    if (b >= g_nseg) return;
    int g = threadIdx.x;

    int nb = g_bounds[b + 1] - g_bounds[b];
    double ic = 1.0 / (4.0 * (double)nb + (double)EPSF);

    double T1 = 0.0, T2 = 0.0;
#pragma unroll
    for (int k = 0; k < 4; k++) {
        T1 += g_sum[b * C_CH + g * 4 + k];
        T2 += g_sqs[b * C_CH + g * 4 + k];
    }
    double m   = T1 * ic;
    double var = (T2 - 2.0 * m * T1 + 4.0 * (double)nb * m * m) * ic;
    double is  = 1.0 / sqrt(var + (double)EPSF);

    float4 sc, sh;
    float wv, bv;
    wv = __ldg(&w[g * 4 + 0]); bv = __ldg(&bias[g * 4 + 0]);
    sc.x = (float)(is * wv);   sh.x = (float)(bv - m * is * wv);
    wv = __ldg(&w[g * 4 + 1]); bv = __ldg(&bias[g * 4 + 1]);
    sc.y = (float)(is * wv);   sh.y = (float)(bv - m * is * wv);
    wv = __ldg(&w[g * 4 + 2]); bv = __ldg(&bias[g * 4 + 2]);
    sc.z = (float)(is * wv);   sh.z = (float)(bv - m * is * wv);
    wv = __ldg(&w[g * 4 + 3]); bv = __ldg(&bias[g * 4 + 3]);
    sc.w = (float)(is * wv);   sh.w = (float)(bv - m * is * wv);

    g_scale[b * NGROUP + g] = sc;
    g_shift[b * NGROUP + g] = sh;

    // restore the zero invariant for the next replay (this block's slice only)
#pragma unroll
    for (int k = 0; k < 4; k++) {
        g_sum[b * C_CH + g * 4 + k] = 0.0;
        g_sqs[b * C_CH + g * 4 + k] = 0.0;
    }
}

// ---------------------------------------------------------------------------
// 3) normalize: inline index arithmetic, no launch bounds (measured-best
//    allocation: 48 regs / 5 CTAs/SM); pure ldcs -> FFMA -> stcs stream.
// ---------------------------------------------------------------------------
__global__ void dogn_norm(const float4* __restrict__ data,
                          float4* __restrict__ out,
                          int n, int rows_per_block) {
    __shared__ int sb[BMAX + 1];
    __shared__ int sB;
    if (threadIdx.x == 0) sB = g_nseg;
    __syncthreads();
    int B = sB;
    for (int j = threadIdx.x; j <= B; j += blockDim.x) sb[j] = g_bounds[j];
    __syncthreads();

    const int lane = threadIdx.x & 31;
    const int rsub = threadIdx.x >> 5;
    int r0 = blockIdx.x * rows_per_block;
    int r1 = r0 + rows_per_block;
    if (r1 > n) r1 = n;
    if (r0 >= r1) return;

    for (int seg = 0; seg < B; seg++) {
        int a = sb[seg], e = sb[seg + 1];
        if (a < r0) a = r0;
        if (e > r1) e = r1;
        if (a >= e) continue;

        float4 sc = g_scale[seg * NGROUP + lane];
        float4 sh = g_shift[seg * NGROUP + lane];

        int r = a + rsub;
        for (; r + 24 < e; r += 32) {
            float4 v0 = __ldcs(&data[(size_t)r * 32 + lane]);
            float4 v1 = __ldcs(&data[(size_t)(r + 8) * 32 + lane]);
            float4 v2 = __ldcs(&data[(size_t)(r + 16) * 32 + lane]);
            float4 v3 = __ldcs(&data[(size_t)(r + 24) * 32 + lane]);
            v0.x = fmaf(v0.x, sc.x, sh.x);
            v0.y = fmaf(v0.y, sc.y, sh.y);
            v0.z = fmaf(v0.z, sc.z, sh.z);
            v0.w = fmaf(v0.w, sc.w, sh.w);
            v1.x = fmaf(v1.x, sc.x, sh.x);
            v1.y = fmaf(v1.y, sc.y, sh.y);
            v1.z = fmaf(v1.z, sc.z, sh.z);
            v1.w = fmaf(v1.w, sc.w, sh.w);
            v2.x = fmaf(v2.x, sc.x, sh.x);
            v2.y = fmaf(v2.y, sc.y, sh.y);
            v2.z = fmaf(v2.z, sc.z, sh.z);
            v2.w = fmaf(v2.w, sc.w, sh.w);
            v3.x = fmaf(v3.x, sc.x, sh.x);
            v3.y = fmaf(v3.y, sc.y, sh.y);
            v3.z = fmaf(v3.z, sc.z, sh.z);
            v3.w = fmaf(v3.w, sc.w, sh.w);
            __stcs(&out[(size_t)r * 32 + lane], v0);
            __stcs(&out[(size_t)(r + 8) * 32 + lane], v1);
            __stcs(&out[(size_t)(r + 16) * 32 + lane], v2);
            __stcs(&out[(size_t)(r + 24) * 32 + lane], v3);
        }
        for (; r < e; r += 8) {
            float4 v = __ldcs(&data[(size_t)r * 32 + lane]);
            v.x = fmaf(v.x, sc.x, sh.x);
            v.y = fmaf(v.y, sc.y, sh.y);
            v.z = fmaf(v.z, sc.z, sh.z);
            v.w = fmaf(v.w, sc.w, sh.w);
            __stcs(&out[(size_t)r * 32 + lane], v);
        }
    }
}

// ---------------------------------------------------------------------------
extern "C" void kernel_launch(void* const* d_in, const int* in_sizes, int n_in,
                              void* d_out, int out_size) {
    const float* data = (const float*)d_in[0];
    const float* w    = (const float*)d_in[1];
    const float* bias = (const float*)d_in[2];
    const int*   bid  = (const int*)d_in[3];
    const int*   bsz  = (const int*)d_in[4];

    int n = in_sizes[0] / C_CH;   // rows

    // 0) bounds only — accumulators arrive zeroed (module init on first call,
    //    finalize re-zeroes after each use).
    dogn_setup<<<1, 128>>>(bid, n, bsz);

    // 1) stats (best measured grid)
    const int SGRID = 3552;
    int srpb = (n + SGRID - 1) / SGRID;
    dogn_stats<<<SGRID, 256>>>((const float4*)data, n, srpb);

    // 2) finalize (+ re-zero accumulators for next replay)
    dogn_finalize<<<BMAX, 32>>>(w, bias);

    // 3) normalize (best measured grid)
    const int NGRID = 2368;
    int nrpb = (n + NGRID - 1) / NGRID;
    dogn_norm<<<NGRID, 256>>>((const float4*)data, (float4*)d_out, n, nrpb);
}

// round 15
// speedup vs baseline: 1.0066x; 1.0011x over previous
#include <cuda_runtime.h>

#define C_CH   128
#define NGROUP 32
#define CPG    4
#define BMAX   64
#define EPSF   1e-5f

// Scratch (no allocations allowed). Zero-initialized at module load; the
// g_sum/g_sqs "zero at stats entry" invariant is restored by dogn_finalize
// re-zeroing its slice after consumption (replay-safe, deterministic).
__device__ double g_sum[BMAX * C_CH];
__device__ double g_sqs[BMAX * C_CH];
__device__ int    g_bounds[BMAX + 1];
__device__ int    g_nseg;
__device__ float4 g_scale[BMAX * NGROUP];
__device__ float4 g_shift[BMAX * NGROUP];

// ---------------------------------------------------------------------------
// 1) stats: block owns contiguous row chunk and discovers its own segment
//    boundaries (chunk-local binary searches — no setup kernel needed).
//    Per segment: pure ldcs->FMA stream (4-row unroll); flush via cross-warp
//    smem reduction, warp 0 issues the atomics.
// ---------------------------------------------------------------------------
#define ACC4(v)                                   \
    s0 += (v).x; q0 = fmaf((v).x, (v).x, q0);     \
    s1 += (v).y; q1 = fmaf((v).y, (v).y, q1);     \
    s2 += (v).z; q2 = fmaf((v).z, (v).z, q2);     \
    s3 += (v).w; q3 = fmaf((v).w, (v).w, q3);

__global__ void dogn_stats(const float4* __restrict__ data,
                           const int* __restrict__ bid,
                           int n, int rows_per_block) {
    __shared__ int   sb[BMAX + 2];
    __shared__ int   s_meta[2];      // [0]=first batch id in chunk, [1]=nseg
    __shared__ float red[8 * 256];   // [k][warp*32 + lane]

    const int tid  = threadIdx.x;
    const int lane = tid & 31;
    const int rsub = tid >> 5;
    int r0 = blockIdx.x * rows_per_block;
    int r1 = r0 + rows_per_block;
    if (r1 > n) r1 = n;
    if (r0 >= r1) return;   // whole block exits together (uniform)

    // chunk-local boundary discovery
    if (tid == 0) {
        int b_lo = __ldg(&bid[r0]);
        int b_hi = __ldg(&bid[r1 - 1]);
        s_meta[0] = b_lo;
        s_meta[1] = b_hi - b_lo + 1;
    }
    __syncthreads();
    const int b0   = s_meta[0];
    const int nseg = s_meta[1];

    if (tid <= nseg) {
        if (tid == 0)            sb[0]    = r0;
        else if (tid == nseg)    sb[nseg] = r1;
        else {
            int key = b0 + tid;          // first row with bid >= key, in [r0,r1)
            int lo = r0, hi = r1;
            while (lo < hi) {
                int mid = (lo + hi) >> 1;
                if (__ldg(&bid[mid]) < key) lo = mid + 1;
                else hi = mid;
            }
            sb[tid] = lo;
        }
    }
    __syncthreads();

    for (int i = 0; i < nseg; i++) {
        int a = sb[i], e = sb[i + 1];
        if (a >= e) continue;            // empty mid-chunk segment (uniform)
        int seg = b0 + i;

        float s0 = 0.f, s1 = 0.f, s2 = 0.f, s3 = 0.f;
        float q0 = 0.f, q1 = 0.f, q2 = 0.f, q3 = 0.f;

        int r = a + rsub;
        for (; r + 24 < e; r += 32) {
            const float4* p = &data[(size_t)r * 32 + lane];
            float4 v0 = __ldcs(p);
            float4 v1 = __ldcs(p + 8 * 32);
            float4 v2 = __ldcs(p + 16 * 32);
            float4 v3 = __ldcs(p + 24 * 32);
            ACC4(v0) ACC4(v1) ACC4(v2) ACC4(v3)
        }
        for (; r < e; r += 8) {
            float4 v = __ldcs(&data[(size_t)r * 32 + lane]);
            ACC4(v)
        }

        red[0 * 256 + tid] = s0;
        red[1 * 256 + tid] = s1;
        red[2 * 256 + tid] = s2;
        red[3 * 256 + tid] = s3;
        red[4 * 256 + tid] = q0;
        red[5 * 256 + tid] = q1;
        red[6 * 256 + tid] = q2;
        red[7 * 256 + tid] = q3;
        __syncthreads();

        if (tid < 32) {
            double* ps = &g_sum[seg * C_CH + tid * 4];
            double* pq = &g_sqs[seg * C_CH + tid * 4];
#pragma unroll
            for (int k = 0; k < 4; k++) {
                float vs = 0.f, vq = 0.f;
#pragma unroll
                for (int w = 0; w < 8; w++) {
                    vs += red[k * 256 + w * 32 + tid];
                    vq += red[(k + 4) * 256 + w * 32 + tid];
                }
                atomicAdd(ps + k, (double)vs);
                atomicAdd(pq + k, (double)vq);
            }
        }
        __syncthreads();
    }
}

// ---------------------------------------------------------------------------
// 2) finalize: one block per batch. Computes its own bounds by binary search,
//    publishes g_bounds/g_nseg for norm, emits folded scale/shift, and
//    re-zeroes its accumulator slice for the next graph replay.
// ---------------------------------------------------------------------------
__device__ __forceinline__ int lb_search(const int* __restrict__ bid, int n, int key) {
    int lo = 0, hi = n;
    while (lo < hi) {
        int mid = (lo + hi) >> 1;
        if (__ldg(&bid[mid]) < key) lo = mid + 1;
        else hi = mid;
    }
    return lo;
}

__global__ void dogn_finalize(const int* __restrict__ bid, int n,
                              const int* __restrict__ bsz_ptr,
                              const float* __restrict__ w,
                              const float* __restrict__ bias) {
    int b = blockIdx.x;
    int B = __ldg(bsz_ptr);
    if (B > BMAX) B = BMAX;
    if (b == 0 && threadIdx.x == 0) g_nseg = B;
    if (b >= B) return;

    __shared__ int bounds[2];
    if (threadIdx.x < 2)
        bounds[threadIdx.x] = lb_search(bid, n, b + threadIdx.x);
    __syncthreads();

    int g = threadIdx.x;   // 0..31 = group

    if (g == 0) {
        g_bounds[b] = bounds[0];
        if (b == B - 1) g_bounds[B] = bounds[1];
    }

    int nb = bounds[1] - bounds[0];
    double ic = 1.0 / (4.0 * (double)nb + (double)EPSF);

    double T1 = 0.0, T2 = 0.0;
#pragma unroll
    for (int k = 0; k < 4; k++) {
        T1 += g_sum[b * C_CH + g * 4 + k];
        T2 += g_sqs[b * C_CH + g * 4 + k];
    }
    double m   = T1 * ic;
    double var = (T2 - 2.0 * m * T1 + 4.0 * (double)nb * m * m) * ic;
    double is  = 1.0 / sqrt(var + (double)EPSF);

    float4 sc, sh;
    float wv, bv;
    wv = __ldg(&w[g * 4 + 0]); bv = __ldg(&bias[g * 4 + 0]);
    sc.x = (float)(is * wv);   sh.x = (float)(bv - m * is * wv);
    wv = __ldg(&w[g * 4 + 1]); bv = __ldg(&bias[g * 4 + 1]);
    sc.y = (float)(is * wv);   sh.y = (float)(bv - m * is * wv);
    wv = __ldg(&w[g * 4 + 2]); bv = __ldg(&bias[g * 4 + 2]);
    sc.z = (float)(is * wv);   sh.z = (float)(bv - m * is * wv);
    wv = __ldg(&w[g * 4 + 3]); bv = __ldg(&bias[g * 4 + 3]);
    sc.w = (float)(is * wv);   sh.w = (float)(bv - m * is * wv);

    g_scale[b * NGROUP + g] = sc;
    g_shift[b * NGROUP + g] = sh;

    // restore the zero invariant for the next replay (this block's slice only)
#pragma unroll
    for (int k = 0; k < 4; k++) {
        g_sum[b * C_CH + g * 4 + k] = 0.0;
        g_sqs[b * C_CH + g * 4 + k] = 0.0;
    }
}

// ---------------------------------------------------------------------------
// 3) normalize: inline index arithmetic, no launch bounds (measured-best
//    allocation: 48 regs / 5 CTAs/SM); pure ldcs -> FFMA -> stcs stream.
//    Reads g_bounds/g_nseg published by finalize.
// ---------------------------------------------------------------------------
__global__ void dogn_norm(const float4* __restrict__ data,
                          float4* __restrict__ out,
                          int n, int rows_per_block) {
    __shared__ int sb[BMAX + 1];
    __shared__ int sB;
    if (threadIdx.x == 0) sB = g_nseg;
    __syncthreads();
    int B = sB;
    for (int j = threadIdx.x; j <= B; j += blockDim.x) sb[j] = g_bounds[j];
    __syncthreads();

    const int lane = threadIdx.x & 31;
    const int rsub = threadIdx.x >> 5;
    int r0 = blockIdx.x * rows_per_block;
    int r1 = r0 + rows_per_block;
    if (r1 > n) r1 = n;
    if (r0 >= r1) return;

    for (int seg = 0; seg < B; seg++) {
        int a = sb[seg], e = sb[seg + 1];
        if (a < r0) a = r0;
        if (e > r1) e = r1;
        if (a >= e) continue;

        float4 sc = g_scale[seg * NGROUP + lane];
        float4 sh = g_shift[seg * NGROUP + lane];

        int r = a + rsub;
        for (; r + 24 < e; r += 32) {
            float4 v0 = __ldcs(&data[(size_t)r * 32 + lane]);
            float4 v1 = __ldcs(&data[(size_t)(r + 8) * 32 + lane]);
            float4 v2 = __ldcs(&data[(size_t)(r + 16) * 32 + lane]);
            float4 v3 = __ldcs(&data[(size_t)(r + 24) * 32 + lane]);
            v0.x = fmaf(v0.x, sc.x, sh.x);
            v0.y = fmaf(v0.y, sc.y, sh.y);
            v0.z = fmaf(v0.z, sc.z, sh.z);
            v0.w = fmaf(v0.w, sc.w, sh.w);
            v1.x = fmaf(v1.x, sc.x, sh.x);
            v1.y = fmaf(v1.y, sc.y, sh.y);
            v1.z = fmaf(v1.z, sc.z, sh.z);
            v1.w = fmaf(v1.w, sc.w, sh.w);
            v2.x = fmaf(v2.x, sc.x, sh.x);
            v2.y = fmaf(v2.y, sc.y, sh.y);
            v2.z = fmaf(v2.z, sc.z, sh.z);
            v2.w = fmaf(v2.w, sc.w, sh.w);
            v3.x = fmaf(v3.x, sc.x, sh.x);
            v3.y = fmaf(v3.y, sc.y, sh.y);
            v3.z = fmaf(v3.z, sc.z, sh.z);
            v3.w = fmaf(v3.w, sc.w, sh.w);
            __stcs(&out[(size_t)r * 32 + lane], v0);
            __stcs(&out[(size_t)(r + 8) * 32 + lane], v1);
            __stcs(&out[(size_t)(r + 16) * 32 + lane], v2);
            __stcs(&out[(size_t)(r + 24) * 32 + lane], v3);
        }
        for (; r < e; r += 8) {
            float4 v = __ldcs(&data[(size_t)r * 32 + lane]);
            v.x = fmaf(v.x, sc.x, sh.x);
            v.y = fmaf(v.y, sc.y, sh.y);
            v.z = fmaf(v.z, sc.z, sh.z);
            v.w = fmaf(v.w, sc.w, sh.w);
            __stcs(&out[(size_t)r * 32 + lane], v);
        }
    }
}

// ---------------------------------------------------------------------------
extern "C" void kernel_launch(void* const* d_in, const int* in_sizes, int n_in,
                              void* d_out, int out_size) {
    const float* data = (const float*)d_in[0];
    const float* w    = (const float*)d_in[1];
    const float* bias = (const float*)d_in[2];
    const int*   bid  = (const int*)d_in[3];
    const int*   bsz  = (const int*)d_in[4];

    int n = in_sizes[0] / C_CH;   // rows

    // 1) stats — self-contained (chunk-local boundary discovery), no setup pass
    const int SGRID = 3552;
    int srpb = (n + SGRID - 1) / SGRID;
    dogn_stats<<<SGRID, 256>>>((const float4*)data, bid, n, srpb);

    // 2) finalize — computes bounds, publishes g_bounds/g_nseg, re-zeros accums
    dogn_finalize<<<BMAX, 32>>>(bid, n, bsz, w, bias);

    // 3) normalize
    const int NGRID = 2368;
    int nrpb = (n + NGRID - 1) / NGRID;
    dogn_norm<<<NGRID, 256>>>((const float4*)data, (float4*)d_out, n, nrpb);
}